// round 1
// baseline (speedup 1.0000x reference)
#include <cuda_runtime.h>
#include <cuda_bf16.h>

// WeightAndSum: out[seg[r], :] += feats[r, :] * sigmoid(dot(feats[r,:], w) + b)
// N = 2,000,000 rows, D = 128, B = 65536 segments, segment_ids sorted ascending.
//
// Strategy: warp-per-row streaming. Each warp owns ROWS_PER_WARP contiguous
// rows. Lane l holds columns [4l, 4l+4). Per-row: one LDG.128/lane, warp
// butterfly-reduce for the dot product, sigmoid, scale, accumulate in regs
// while segment id unchanged. Segments fully interior to a warp's chunk are
// flushed with a plain float4 store (exclusive by sortedness, out pre-zeroed);
// boundary segments flushed with atomicAdd.

#define D_DIM 128
#define ROWS_PER_WARP 128
#define THREADS 256

__global__ __launch_bounds__(THREADS) void was_kernel(
    const float* __restrict__ feats,
    const int*   __restrict__ seg,
    const float* __restrict__ w,
    const float* __restrict__ b,
    float*       __restrict__ out,
    int N)
{
    const int gwarp = (blockIdx.x * THREADS + threadIdx.x) >> 5;
    const int lane  = threadIdx.x & 31;

    long start = (long)gwarp * ROWS_PER_WARP;
    if (start >= N) return;
    long end = start + ROWS_PER_WARP;
    if (end > N) end = N;

    const float4 wv  = reinterpret_cast<const float4*>(w)[lane];
    const float bias = __ldg(b);

    float4 acc = make_float4(0.f, 0.f, 0.f, 0.f);
    int  cur = __ldg(&seg[start]);
    bool started_inside = false;  // segment began strictly inside this chunk

    for (long r = start; r < end; ++r) {
        const int s = __ldg(&seg[r]);
        if (s != cur) {
            // flush completed segment 'cur'
            float* o = out + (size_t)cur * D_DIM + lane * 4;
            if (started_inside) {
                // began AND ended inside this warp's chunk -> exclusive
                *reinterpret_cast<float4*>(o) = acc;
            } else {
                atomicAdd(o + 0, acc.x);
                atomicAdd(o + 1, acc.y);
                atomicAdd(o + 2, acc.z);
                atomicAdd(o + 3, acc.w);
            }
            acc = make_float4(0.f, 0.f, 0.f, 0.f);
            cur = s;
            started_inside = true;
        }

        const float4 f = reinterpret_cast<const float4*>(feats + (size_t)r * D_DIM)[lane];

        // dot(row, w): per-lane partial then butterfly reduce across warp
        float p = f.x * wv.x + f.y * wv.y + f.z * wv.z + f.w * wv.w;
        p += __shfl_xor_sync(0xffffffffu, p, 16);
        p += __shfl_xor_sync(0xffffffffu, p, 8);
        p += __shfl_xor_sync(0xffffffffu, p, 4);
        p += __shfl_xor_sync(0xffffffffu, p, 2);
        p += __shfl_xor_sync(0xffffffffu, p, 1);

        const float g = 1.0f / (1.0f + __expf(-(p + bias)));

        acc.x += f.x * g;
        acc.y += f.y * g;
        acc.z += f.z * g;
        acc.w += f.w * g;
    }

    // final segment may continue into the next warp's chunk -> atomic
    float* o = out + (size_t)cur * D_DIM + lane * 4;
    atomicAdd(o + 0, acc.x);
    atomicAdd(o + 1, acc.y);
    atomicAdd(o + 2, acc.z);
    atomicAdd(o + 3, acc.w);
}

extern "C" void kernel_launch(void* const* d_in, const int* in_sizes, int n_in,
                              void* d_out, int out_size)
{
    const float* feats = (const float*)d_in[0];
    const int*   seg   = (const int*)d_in[1];
    const float* w     = (const float*)d_in[2];
    const float* b     = (const float*)d_in[3];
    float*       out   = (float*)d_out;

    const int N = in_sizes[1];  // element count of segment_ids == N rows

    // output is poisoned; zero it (graph-capturable async memset)
    cudaMemsetAsync(d_out, 0, (size_t)out_size * sizeof(float), 0);

    const int warps  = (N + ROWS_PER_WARP - 1) / ROWS_PER_WARP;
    const int blocks = (warps * 32 + THREADS - 1) / THREADS;
    was_kernel<<<blocks, THREADS>>>(feats, seg, w, b, out, N);
}

// round 2
// speedup vs baseline: 1.4831x; 1.4831x over previous
#include <cuda_runtime.h>
#include <cuda_bf16.h>

// WeightAndSum: out[seg[r], :] += feats[r, :] * sigmoid(dot(feats[r,:], w) + b)
// N = 2,000,000 rows, D = 128, B = 65536 segments, segment_ids sorted ascending.
//
// Warp-per-row streaming, unrolled 4 rows/iter for MLP. Lane l holds columns
// [4l, 4l+4). Interior segments flushed with plain float4 store (exclusive by
// sortedness, out pre-zeroed); boundary segments flushed with atomicAdd.

#define D_DIM 128
#define ROWS_PER_WARP 128
#define THREADS 256

__global__ __launch_bounds__(THREADS) void was_kernel(
    const float* __restrict__ feats,
    const int*   __restrict__ seg,
    const float* __restrict__ w,
    const float* __restrict__ b,
    float*       __restrict__ out,
    int N)
{
    const int gwarp = (blockIdx.x * THREADS + threadIdx.x) >> 5;
    const int lane  = threadIdx.x & 31;

    long start = (long)gwarp * ROWS_PER_WARP;
    if (start >= N) return;
    long end = start + ROWS_PER_WARP;
    if (end > N) end = N;

    const float4 wv  = reinterpret_cast<const float4*>(w)[lane];
    const float bias = __ldg(b);

    float4 acc = make_float4(0.f, 0.f, 0.f, 0.f);
    int  cur = __ldg(&seg[start]);
    bool started_inside = false;  // current segment began strictly inside chunk

    // flush helper expanded inline via macro (branch rarely taken)
#define PROC_ROW(S, F, G)                                                   \
    do {                                                                    \
        if ((S) != cur) {                                                   \
            float* o = out + (size_t)cur * D_DIM + lane * 4;                \
            if (started_inside) {                                           \
                *reinterpret_cast<float4*>(o) = acc;                        \
            } else {                                                        \
                atomicAdd(o + 0, acc.x);                                    \
                atomicAdd(o + 1, acc.y);                                    \
                atomicAdd(o + 2, acc.z);                                    \
                atomicAdd(o + 3, acc.w);                                    \
            }                                                               \
            acc = make_float4(0.f, 0.f, 0.f, 0.f);                          \
            cur = (S);                                                      \
            started_inside = true;                                          \
        }                                                                   \
        acc.x += (F).x * (G);                                               \
        acc.y += (F).y * (G);                                               \
        acc.z += (F).z * (G);                                               \
        acc.w += (F).w * (G);                                               \
    } while (0)

    long r = start;
    for (; r + 4 <= end; r += 4) {
        // front-batched loads: 4x LDG.128 + 1x LDG.128 (seg) -> high MLP
        const int4 s4 = *reinterpret_cast<const int4*>(seg + r);
        const float4* base =
            reinterpret_cast<const float4*>(feats + (size_t)r * D_DIM) + lane;
        const float4 f0 = __ldcs(base);
        const float4 f1 = __ldcs(base + D_DIM / 4);
        const float4 f2 = __ldcs(base + 2 * (D_DIM / 4));
        const float4 f3 = __ldcs(base + 3 * (D_DIM / 4));

        float p0 = f0.x * wv.x + f0.y * wv.y + f0.z * wv.z + f0.w * wv.w;
        float p1 = f1.x * wv.x + f1.y * wv.y + f1.z * wv.z + f1.w * wv.w;
        float p2 = f2.x * wv.x + f2.y * wv.y + f2.z * wv.z + f2.w * wv.w;
        float p3 = f3.x * wv.x + f3.y * wv.y + f3.z * wv.z + f3.w * wv.w;

        // 4 independent butterfly chains -> pipelined through SHFL unit
#pragma unroll
        for (int o = 16; o > 0; o >>= 1) {
            p0 += __shfl_xor_sync(0xffffffffu, p0, o);
            p1 += __shfl_xor_sync(0xffffffffu, p1, o);
            p2 += __shfl_xor_sync(0xffffffffu, p2, o);
            p3 += __shfl_xor_sync(0xffffffffu, p3, o);
        }

        const float g0 = 1.0f / (1.0f + __expf(-(p0 + bias)));
        const float g1 = 1.0f / (1.0f + __expf(-(p1 + bias)));
        const float g2 = 1.0f / (1.0f + __expf(-(p2 + bias)));
        const float g3 = 1.0f / (1.0f + __expf(-(p3 + bias)));

        PROC_ROW(s4.x, f0, g0);
        PROC_ROW(s4.y, f1, g1);
        PROC_ROW(s4.z, f2, g2);
        PROC_ROW(s4.w, f3, g3);
    }

    // tail (not taken for N = 2M: all chunks are full multiples of 4)
    for (; r < end; ++r) {
        const int s = __ldg(&seg[r]);
        const float4 f =
            reinterpret_cast<const float4*>(feats + (size_t)r * D_DIM)[lane];
        float p = f.x * wv.x + f.y * wv.y + f.z * wv.z + f.w * wv.w;
#pragma unroll
        for (int o = 16; o > 0; o >>= 1) p += __shfl_xor_sync(0xffffffffu, p, o);
        const float g = 1.0f / (1.0f + __expf(-(p + bias)));
        PROC_ROW(s, f, g);
    }
#undef PROC_ROW

    // final segment may continue into the next warp's chunk -> atomic
    float* o = out + (size_t)cur * D_DIM + lane * 4;
    atomicAdd(o + 0, acc.x);
    atomicAdd(o + 1, acc.y);
    atomicAdd(o + 2, acc.z);
    atomicAdd(o + 3, acc.w);
}

extern "C" void kernel_launch(void* const* d_in, const int* in_sizes, int n_in,
                              void* d_out, int out_size)
{
    const float* feats = (const float*)d_in[0];
    const int*   seg   = (const int*)d_in[1];
    const float* w     = (const float*)d_in[2];
    const float* b     = (const float*)d_in[3];
    float*       out   = (float*)d_out;

    const int N = in_sizes[1];  // element count of segment_ids == N rows

    cudaMemsetAsync(d_out, 0, (size_t)out_size * sizeof(float), 0);

    const int warps  = (N + ROWS_PER_WARP - 1) / ROWS_PER_WARP;
    const int blocks = (warps * 32 + THREADS - 1) / THREADS;
    was_kernel<<<blocks, THREADS>>>(feats, seg, w, b, out, N);
}

// round 3
// speedup vs baseline: 1.5279x; 1.0302x over previous
#include <cuda_runtime.h>
#include <cuda_bf16.h>

// WeightAndSum: out[seg[r], :] += feats[r, :] * sigmoid(dot(feats[r,:], w) + b)
// N = 2,000,000 rows, D = 128, B = 65536 segments, segment_ids sorted ascending.
//
// Warp-per-row streaming, 4 rows/iter, explicit register double-buffering:
// iteration i+1's loads are issued before iteration i's compute chain and
// flush branches, so DRAM latency is hidden behind the SHFL/MUFU chain.
// Interior segments flushed with plain float4 store (exclusive by sortedness,
// out pre-zeroed); boundary segments flushed with atomicAdd.

#define D_DIM 128
#define ROWS_PER_WARP 128
#define THREADS 256

__global__ __launch_bounds__(THREADS) void was_kernel(
    const float* __restrict__ feats,
    const int*   __restrict__ seg,
    const float* __restrict__ w,
    const float* __restrict__ b,
    float*       __restrict__ out,
    int N)
{
    const int gwarp = (blockIdx.x * THREADS + threadIdx.x) >> 5;
    const int lane  = threadIdx.x & 31;

    long start = (long)gwarp * ROWS_PER_WARP;
    if (start >= N) return;
    long end = start + ROWS_PER_WARP;
    if (end > N) end = N;

    const float4 wv  = reinterpret_cast<const float4*>(w)[lane];
    const float bias = __ldg(b);

    float4 acc = make_float4(0.f, 0.f, 0.f, 0.f);
    int  cur = __ldg(&seg[start]);
    bool started_inside = false;  // current segment began strictly inside chunk

#define PROC_ROW(S, F, G)                                                   \
    do {                                                                    \
        if ((S) != cur) {                                                   \
            float* o = out + (size_t)cur * D_DIM + lane * 4;                \
            if (started_inside) {                                           \
                *reinterpret_cast<float4*>(o) = acc;                        \
            } else {                                                        \
                atomicAdd(o + 0, acc.x);                                    \
                atomicAdd(o + 1, acc.y);                                    \
                atomicAdd(o + 2, acc.z);                                    \
                atomicAdd(o + 3, acc.w);                                    \
            }                                                               \
            acc = make_float4(0.f, 0.f, 0.f, 0.f);                          \
            cur = (S);                                                      \
            started_inside = true;                                          \
        }                                                                   \
        acc.x += (F).x * (G);                                               \
        acc.y += (F).y * (G);                                               \
        acc.z += (F).z * (G);                                               \
        acc.w += (F).w * (G);                                               \
    } while (0)

    long r = start;
    const long stop = start + ((end - start) & ~3L);  // full 4-row groups

    if (r < stop) {
        // ---- prologue: load group 0 ----
        int4 s4 = *reinterpret_cast<const int4*>(seg + r);
        const float4* base =
            reinterpret_cast<const float4*>(feats + (size_t)r * D_DIM) + lane;
        float4 f0 = __ldcs(base);
        float4 f1 = __ldcs(base + (D_DIM / 4));
        float4 f2 = __ldcs(base + 2 * (D_DIM / 4));
        float4 f3 = __ldcs(base + 3 * (D_DIM / 4));

        for (;;) {
            const long rn = r + 4;
            const bool more = (rn < stop);

            // ---- prefetch group i+1 (issued before current chain/branches) ----
            int4 s4n;
            float4 f0n, f1n, f2n, f3n;
            if (more) {
                s4n = *reinterpret_cast<const int4*>(seg + rn);
                const float4* bn =
                    reinterpret_cast<const float4*>(feats + (size_t)rn * D_DIM) + lane;
                f0n = __ldcs(bn);
                f1n = __ldcs(bn + (D_DIM / 4));
                f2n = __ldcs(bn + 2 * (D_DIM / 4));
                f3n = __ldcs(bn + 3 * (D_DIM / 4));
            }

            // ---- process group i ----
            float p0 = f0.x * wv.x + f0.y * wv.y + f0.z * wv.z + f0.w * wv.w;
            float p1 = f1.x * wv.x + f1.y * wv.y + f1.z * wv.z + f1.w * wv.w;
            float p2 = f2.x * wv.x + f2.y * wv.y + f2.z * wv.z + f2.w * wv.w;
            float p3 = f3.x * wv.x + f3.y * wv.y + f3.z * wv.z + f3.w * wv.w;

#pragma unroll
            for (int o = 16; o > 0; o >>= 1) {
                p0 += __shfl_xor_sync(0xffffffffu, p0, o);
                p1 += __shfl_xor_sync(0xffffffffu, p1, o);
                p2 += __shfl_xor_sync(0xffffffffu, p2, o);
                p3 += __shfl_xor_sync(0xffffffffu, p3, o);
            }

            const float g0 = 1.0f / (1.0f + __expf(-(p0 + bias)));
            const float g1 = 1.0f / (1.0f + __expf(-(p1 + bias)));
            const float g2 = 1.0f / (1.0f + __expf(-(p2 + bias)));
            const float g3 = 1.0f / (1.0f + __expf(-(p3 + bias)));

            PROC_ROW(s4.x, f0, g0);
            PROC_ROW(s4.y, f1, g1);
            PROC_ROW(s4.z, f2, g2);
            PROC_ROW(s4.w, f3, g3);

            if (!more) { r = rn; break; }

            // ---- rotate buffers ----
            s4 = s4n; f0 = f0n; f1 = f1n; f2 = f2n; f3 = f3n;
            r = rn;
        }
    }

    // tail rows (end-start not multiple of 4; unused for N = 2M)
    for (; r < end; ++r) {
        const int s = __ldg(&seg[r]);
        const float4 f =
            reinterpret_cast<const float4*>(feats + (size_t)r * D_DIM)[lane];
        float p = f.x * wv.x + f.y * wv.y + f.z * wv.z + f.w * wv.w;
#pragma unroll
        for (int o = 16; o > 0; o >>= 1) p += __shfl_xor_sync(0xffffffffu, p, o);
        const float g = 1.0f / (1.0f + __expf(-(p + bias)));
        PROC_ROW(s, f, g);
    }
#undef PROC_ROW

    // final segment may continue into the next warp's chunk -> atomic
    float* o = out + (size_t)cur * D_DIM + lane * 4;
    atomicAdd(o + 0, acc.x);
    atomicAdd(o + 1, acc.y);
    atomicAdd(o + 2, acc.z);
    atomicAdd(o + 3, acc.w);
}

extern "C" void kernel_launch(void* const* d_in, const int* in_sizes, int n_in,
                              void* d_out, int out_size)
{
    const float* feats = (const float*)d_in[0];
    const int*   seg   = (const int*)d_in[1];
    const float* w     = (const float*)d_in[2];
    const float* b     = (const float*)d_in[3];
    float*       out   = (float*)d_out;

    const int N = in_sizes[1];  // element count of segment_ids == N rows

    cudaMemsetAsync(d_out, 0, (size_t)out_size * sizeof(float), 0);

    const int warps  = (N + ROWS_PER_WARP - 1) / ROWS_PER_WARP;
    const int blocks = (warps * 32 + THREADS - 1) / THREADS;
    was_kernel<<<blocks, THREADS>>>(feats, seg, w, b, out, N);
}